// round 1
// baseline (speedup 1.0000x reference)
#include <cuda_runtime.h>

// VectorNormSelection: per row of 192 floats (64 vectors of 3), compute squared
// norms, select top-16 by norm (descending, ties -> lower index first, matching
// jax.lax.top_k), gather the selected 3-vectors in that order.
//
// Design: one THREAD per row (32 rows per warp). Rows are staged through
// shared memory with coalesced float4 loads (padded to 196 floats/row for
// conflict-free LDS.128). Each thread maintains a sorted 16-slot (value,index)
// list in registers and does a branch-free sorted insert for each of its 64
// norms (16 FSETP + 64 SELP per insert). Output assembled in registers and
// written as 12 STG.128 per thread.

#define ROW_F     192
#define ROW_F4    48
#define PAD_F     196          // padded floats per row in smem (784B = 49*16)
#define NVOUT     16
#define ROWS_PER_BLOCK 32      // one warp per block, thread-per-row

__device__ __forceinline__ void insert16(float v, int id, float (&bv)[NVOUT], int (&bi)[NVOUT]) {
    bool p[NVOUT];
#pragma unroll
    for (int i = 0; i < NVOUT; i++) p[i] = v > bv[i];
#pragma unroll
    for (int i = NVOUT - 1; i >= 1; i--) {
        bv[i] = p[i - 1] ? bv[i - 1] : (p[i] ? v  : bv[i]);
        bi[i] = p[i - 1] ? bi[i - 1] : (p[i] ? id : bi[i]);
    }
    bv[0] = p[0] ? v  : bv[0];
    bi[0] = p[0] ? id : bi[0];
}

__global__ void __launch_bounds__(ROWS_PER_BLOCK)
vecnorm_topk_kernel(const float* __restrict__ x, float* __restrict__ out, int nrows)
{
    __shared__ float ws[ROWS_PER_BLOCK * PAD_F];

    const int lane    = threadIdx.x;          // 0..31
    const int rowBase = blockIdx.x * ROWS_PER_BLOCK;
    if (rowBase >= nrows) return;
    const int rowsHere = min(ROWS_PER_BLOCK, nrows - rowBase);
    const int total4   = rowsHere * ROW_F4;

    // ---- stage: coalesced global float4 loads -> padded smem rows ----
    const float4* gx = reinterpret_cast<const float4*>(x) + (size_t)rowBase * ROW_F4;
    {
        int r = 0, p = lane;                  // g = lane (< 48), so r=0, p=lane
#pragma unroll 3
        for (int k = 0; k < 48; k++) {
            int g = lane + 32 * k;
            if (g < total4) {
                float4 v = gx[g];
                *reinterpret_cast<float4*>(ws + r * PAD_F + p * 4) = v;
            }
            p += 32;
            if (p >= ROW_F4) { p -= ROW_F4; r += 1; }
        }
    }
    __syncwarp();

    const bool active = (lane < rowsHere);
    const float* sr = ws + lane * PAD_F;      // in-bounds even for inactive lanes

    // ---- norms + branch-free sorted top-16 insert ----
    float bv[NVOUT];
    int   bi[NVOUT];
#pragma unroll
    for (int i = 0; i < NVOUT; i++) { bv[i] = -1.0f; bi[i] = 0; }

#pragma unroll 1
    for (int k = 0; k < 16; k++) {            // 4 vectors (12 floats) per iter
        const float4* s4 = reinterpret_cast<const float4*>(sr + k * 12);
        float4 a = s4[0];
        float4 b = s4[1];
        float4 c = s4[2];
        float n0 = a.x * a.x + a.y * a.y + a.z * a.z;
        float n1 = a.w * a.w + b.x * b.x + b.y * b.y;
        float n2 = b.z * b.z + b.w * b.w + c.x * c.x;
        float n3 = c.y * c.y + c.z * c.z + c.w * c.w;
        int id0 = 4 * k;
        insert16(n0, id0 + 0, bv, bi);
        insert16(n1, id0 + 1, bv, bi);
        insert16(n2, id0 + 2, bv, bi);
        insert16(n3, id0 + 3, bv, bi);
    }

    // ---- gather selected vectors, write 48 floats as 12 x STG.128 ----
    if (active) {
        float o[48];
#pragma unroll
        for (int j = 0; j < NVOUT; j++) {
            const float* vp = sr + bi[j] * 3;
            o[3 * j + 0] = vp[0];
            o[3 * j + 1] = vp[1];
            o[3 * j + 2] = vp[2];
        }
        float4* op = reinterpret_cast<float4*>(out + (size_t)(rowBase + lane) * 48);
#pragma unroll
        for (int q = 0; q < 12; q++)
            op[q] = make_float4(o[4 * q + 0], o[4 * q + 1], o[4 * q + 2], o[4 * q + 3]);
    }
}

extern "C" void kernel_launch(void* const* d_in, const int* in_sizes, int n_in,
                              void* d_out, int out_size)
{
    const float* x   = (const float*)d_in[0];
    float*       out = (float*)d_out;
    int nrows = in_sizes[0] / ROW_F;
    int grid  = (nrows + ROWS_PER_BLOCK - 1) / ROWS_PER_BLOCK;
    vecnorm_topk_kernel<<<grid, ROWS_PER_BLOCK>>>(x, out, nrows);
}